// round 1
// baseline (speedup 1.0000x reference)
#include <cuda_runtime.h>

#define Bn   1024
#define Kseg 160
#define WS   12
#define G    36
#define DH   1024

// Scratch (static device globals — no allocation)
__device__ float g_gi1[Kseg * Bn * G];     // [k][b][36]  input-side gates (shared by both GRU passes)
__device__ float g_pegi[Kseg * G];         // (pe[k]+ch[k]) @ Wih^T
__device__ float g_weff[Kseg * WS * WS];   // folded decoder W1@W2 per segment
__device__ float g_beff[Kseg * WS];        // folded decoder bias
__device__ float g_ys[Bn * Kseg * WS];     // [b][k][12]  GRU2 outputs

// ---------------------------------------------------------------------------
// Kernel 1: encoder (relu(xb@enc_W + enc_b)) and gi1 = xs@Wih^T + bih
// one thread per (b,k); warp shares k (k = tid>>10) so gi writes are coalesced
// ---------------------------------------------------------------------------
__global__ void enc_gi_kernel(const float* __restrict__ x,
                              const float* __restrict__ enc_W,
                              const float* __restrict__ enc_b,
                              const float* __restrict__ Wih,
                              const float* __restrict__ bih) {
    int tid = blockIdx.x * blockDim.x + threadIdx.x;
    int k = tid >> 10;        // / 1024
    int b = tid & 1023;
    if (k >= Kseg) return;

    const float* xr = x + b * 1920 + k * WS;
    float xv[WS];
#pragma unroll
    for (int i = 0; i < WS; ++i) xv[i] = xr[i];

    const float* ew = enc_W + k * (WS * WS);
    float xs[WS];
#pragma unroll
    for (int o = 0; o < WS; ++o) {
        float a = enc_b[k * WS + o];
#pragma unroll
        for (int i = 0; i < WS; ++i) a = fmaf(xv[i], ew[i * WS + o], a);
        xs[o] = fmaxf(a, 0.0f);
    }

    float* gout = g_gi1 + (k * Bn + b) * G;
#pragma unroll
    for (int g = 0; g < G; ++g) {
        float a = bih[g];
#pragma unroll
        for (int o = 0; o < WS; ++o) a = fmaf(xs[o], Wih[g * WS + o], a);
        gout[g] = a;
    }
}

// ---------------------------------------------------------------------------
// Kernel 2: positional-encoding gate table: pe_gi[k][g] = (pe[k]+ch[k])@Wih[g]
// pe = sinusoidal_pe(160,12); channel_enc[k][*] = sin(k) (ch_pe column 0)
// ---------------------------------------------------------------------------
__global__ void pegi_kernel(const float* __restrict__ Wih) {
    int k = threadIdx.x;
    if (k >= Kseg) return;
    float pe[WS];
    const float c = -9.210340371976184f / 12.0f;   // -ln(10000)/d
#pragma unroll
    for (int j = 0; j < 6; ++j) {
        float div = expf(c * (float)(2 * j));
        float ang = (float)k * div;
        pe[2 * j]     = sinf(ang);
        pe[2 * j + 1] = cosf(ang);
    }
    float ch = sinf((float)k);
#pragma unroll
    for (int o = 0; o < WS; ++o) pe[o] += ch;
#pragma unroll
    for (int g = 0; g < G; ++g) {
        float a = 0.0f;
#pragma unroll
        for (int o = 0; o < WS; ++o) a = fmaf(pe[o], Wih[g * WS + o], a);
        g_pegi[k * G + g] = a;
    }
}

// ---------------------------------------------------------------------------
// Kernel 3: decoder fold. Weff[k] = W1[k] @ W2[k]  (12x1024 @ 1024x12),
// beff[k] = b1[k] @ W2[k] + b2[k].  W2 staged in shared memory.
// ---------------------------------------------------------------------------
__global__ void weff_kernel(const float* __restrict__ dec_W1,
                            const float* __restrict__ dec_b1,
                            const float* __restrict__ dec_W2,
                            const float* __restrict__ dec_b2) {
    __shared__ float w2s[DH * WS];   // 48 KB
    int k = blockIdx.x;
    const float* W2 = dec_W2 + k * DH * WS;
    for (int i = threadIdx.x; i < DH * WS; i += blockDim.x) w2s[i] = W2[i];
    __syncthreads();

    int t = threadIdx.x;
    if (t < 144) {
        int d = t / WS, o = t - (t / WS) * WS;
        const float* w1 = dec_W1 + (k * WS + d) * DH;
        float a0 = 0.f, a1 = 0.f, a2 = 0.f, a3 = 0.f;
#pragma unroll 4
        for (int h = 0; h < DH; h += 4) {
            a0 = fmaf(w1[h],     w2s[(h)     * WS + o], a0);
            a1 = fmaf(w1[h + 1], w2s[(h + 1) * WS + o], a1);
            a2 = fmaf(w1[h + 2], w2s[(h + 2) * WS + o], a2);
            a3 = fmaf(w1[h + 3], w2s[(h + 3) * WS + o], a3);
        }
        g_weff[k * 144 + d * WS + o] = (a0 + a1) + (a2 + a3);
    } else if (t < 156) {
        int o = t - 144;
        const float* b1 = dec_b1 + k * DH;
        float a = dec_b2[k * WS + o];
        for (int h = 0; h < DH; ++h) a = fmaf(b1[h], w2s[h * WS + o], a);
        g_beff[k * WS + o] = a;
    }
}

// ---------------------------------------------------------------------------
// Kernel 4: the recurrence. Two GRU passes (320 sequential steps).
// 16-lane group per batch row, lanes 0..11 active (hidden component j).
// Whh rows in registers; h broadcast via shfl; gi software-pipelined 2 steps.
// ---------------------------------------------------------------------------
__device__ __forceinline__ float fast_sigmoid(float v) {
    return __fdividef(1.0f, 1.0f + __expf(-v));
}
__device__ __forceinline__ float fast_tanh(float v) {
    float e = __expf(-2.0f * v);
    return __fdividef(1.0f - e, 1.0f + e);
}

__global__ void __launch_bounds__(128) rnn_kernel(const float* __restrict__ Whh,
                                                  const float* __restrict__ bhh) {
    __shared__ float pegis[Kseg * G];   // 23 KB
    int j16 = threadIdx.x & 15;
    int row = blockIdx.x * 8 + (threadIdx.x >> 4);
    bool act = (j16 < WS);
    int j = act ? j16 : 0;

    float wr[12], wz[12], wn[12];
#pragma unroll
    for (int i = 0; i < 12; ++i) {
        wr[i] = Whh[j * 12 + i];
        wz[i] = Whh[(12 + j) * 12 + i];
        wn[i] = Whh[(24 + j) * 12 + i];
    }
    float br = bhh[j], bz = bhh[12 + j], bn = bhh[24 + j];

    for (int i = threadIdx.x; i < Kseg * G; i += 128) pegis[i] = g_pegi[i];
    __syncthreads();

    const float* gbase = g_gi1 + row * G;
    float h = 0.0f;

    float gr0, gz0, gn0, gr1, gz1, gn1;

    // ---------------- phase 1: first GRU (keep only final h) ---------------
    {
        const float* g0 = gbase;
        gr0 = g0[j]; gz0 = g0[12 + j]; gn0 = g0[24 + j];
        const float* g1 = gbase + (Bn * G);
        gr1 = g1[j]; gz1 = g1[12 + j]; gn1 = g1[24 + j];
    }
    for (int t = 0; t < Kseg; ++t) {
        float gr = gr0, gz = gz0, gn = gn0;
        gr0 = gr1; gz0 = gz1; gn0 = gn1;
        int tp = (t + 2 < Kseg) ? t + 2 : Kseg - 1;
        const float* gp = gbase + tp * (Bn * G);
        gr1 = gp[j]; gz1 = gp[12 + j]; gn1 = gp[24 + j];

        float a0 = br, a1 = 0.f, b0 = bz, b1 = 0.f, c0 = bn, c1 = 0.f;
#pragma unroll
        for (int i = 0; i < 12; i += 2) {
            float h0v = __shfl_sync(0xffffffffu, h, i, 16);
            float h1v = __shfl_sync(0xffffffffu, h, i + 1, 16);
            a0 = fmaf(wr[i], h0v, a0); a1 = fmaf(wr[i + 1], h1v, a1);
            b0 = fmaf(wz[i], h0v, b0); b1 = fmaf(wz[i + 1], h1v, b1);
            c0 = fmaf(wn[i], h0v, c0); c1 = fmaf(wn[i + 1], h1v, c1);
        }
        float r = fast_sigmoid(gr + (a0 + a1));
        float z = fast_sigmoid(gz + (b0 + b1));
        float n = fast_tanh(fmaf(r, c0 + c1, gn));
        h = fmaf(z, h - n, n);
    }

    // ---------------- phase 2: second GRU (emit all outputs) ---------------
    float* yo = g_ys + row * (Kseg * WS);
    {
        const float* g0 = gbase;
        gr0 = g0[j]; gz0 = g0[12 + j]; gn0 = g0[24 + j];
        const float* g1 = gbase + (Bn * G);
        gr1 = g1[j]; gz1 = g1[12 + j]; gn1 = g1[24 + j];
    }
    for (int t = 0; t < Kseg; ++t) {
        const float* p = pegis + t * G;
        float gr = gr0 + p[j], gz = gz0 + p[12 + j], gn = gn0 + p[24 + j];
        gr0 = gr1; gz0 = gz1; gn0 = gn1;
        int tp = (t + 2 < Kseg) ? t + 2 : Kseg - 1;
        const float* gp = gbase + tp * (Bn * G);
        gr1 = gp[j]; gz1 = gp[12 + j]; gn1 = gp[24 + j];

        float a0 = br, a1 = 0.f, b0 = bz, b1 = 0.f, c0 = bn, c1 = 0.f;
#pragma unroll
        for (int i = 0; i < 12; i += 2) {
            float h0v = __shfl_sync(0xffffffffu, h, i, 16);
            float h1v = __shfl_sync(0xffffffffu, h, i + 1, 16);
            a0 = fmaf(wr[i], h0v, a0); a1 = fmaf(wr[i + 1], h1v, a1);
            b0 = fmaf(wz[i], h0v, b0); b1 = fmaf(wz[i + 1], h1v, b1);
            c0 = fmaf(wn[i], h0v, c0); c1 = fmaf(wn[i + 1], h1v, c1);
        }
        float r = fast_sigmoid(gr + (a0 + a1));
        float z = fast_sigmoid(gz + (b0 + b1));
        float n = fast_tanh(fmaf(r, c0 + c1, gn));
        h = fmaf(z, h - n, n);
        if (act) yo[t * WS + j] = h;
    }
}

// ---------------------------------------------------------------------------
// Kernel 5: folded decoder: out[b,k,:] = ys[b,k,:] @ Weff[k] + beff[k]
// warp covers consecutive k of same b -> fully coalesced ys reads / out writes
// ---------------------------------------------------------------------------
__global__ void dec_kernel(float* __restrict__ out) {
    int tid = blockIdx.x * blockDim.x + threadIdx.x;
    int b = tid / Kseg;
    int k = tid - b * Kseg;
    if (b >= Bn) return;

    const float* hp = g_ys + (b * Kseg + k) * WS;
    float hv[WS];
#pragma unroll
    for (int d = 0; d < WS; ++d) hv[d] = hp[d];

    const float* w  = g_weff + k * 144;
    const float* be = g_beff + k * WS;
    float* op = out + b * 1920 + k * WS;
#pragma unroll
    for (int o = 0; o < WS; ++o) {
        float a = be[o];
#pragma unroll
        for (int d = 0; d < WS; ++d) a = fmaf(hv[d], w[d * WS + o], a);
        op[o] = a;
    }
}

// ---------------------------------------------------------------------------
extern "C" void kernel_launch(void* const* d_in, const int* in_sizes, int n_in,
                              void* d_out, int out_size) {
    const float* x     = (const float*)d_in[0];
    const float* enc_W = (const float*)d_in[1];
    const float* enc_b = (const float*)d_in[2];
    const float* Wih   = (const float*)d_in[3];
    const float* Whh   = (const float*)d_in[4];
    const float* bih   = (const float*)d_in[5];
    const float* bhh   = (const float*)d_in[6];
    const float* dW1   = (const float*)d_in[7];
    const float* db1   = (const float*)d_in[8];
    const float* dW2   = (const float*)d_in[9];
    const float* db2   = (const float*)d_in[10];
    float* out = (float*)d_out;

    enc_gi_kernel<<<640, 256>>>(x, enc_W, enc_b, Wih, bih);   // 1024*160 threads
    pegi_kernel<<<1, 192>>>(Wih);
    weff_kernel<<<Kseg, 256>>>(dW1, db1, dW2, db2);
    rnn_kernel<<<128, 128>>>(Whh, bhh);                       // 1024 rows, 16 lanes each
    dec_kernel<<<640, 256>>>(out);
}

// round 2
// speedup vs baseline: 1.0919x; 1.0919x over previous
#include <cuda_runtime.h>

#define Bn   1024
#define Kseg 160
#define WS   12
#define G    36
#define DH   1024

// Scratch (static device globals — no allocation)
__device__ float g_gi1[Kseg * Bn * G];     // [k][b][36]  input-side gates
__device__ float g_pegi[Kseg * G];         // (pe[k]+ch[k]) @ Wih^T
__device__ float g_weff[Kseg * WS * WS];   // folded decoder W1@W2 per segment
__device__ float g_beff[Kseg * WS];        // folded decoder bias
__device__ float g_ys[Bn * Kseg * WS];     // [b][k][12]  GRU2 outputs

// ---------------------------------------------------------------------------
// Kernel 1: encoder relu(xb@enc_W+enc_b) and gi1 = xs@Wih^T + bih.
// Block = 256 threads = 256 consecutive b, one k. Results staged in padded
// smem then written out fully coalesced.
// ---------------------------------------------------------------------------
__global__ void __launch_bounds__(256) enc_gi_kernel(
        const float* __restrict__ x,
        const float* __restrict__ enc_W,
        const float* __restrict__ enc_b,
        const float* __restrict__ Wih,
        const float* __restrict__ bih) {
    __shared__ float sg[256 * 37];          // pad 36->37: conflict-free STS
    int k = blockIdx.x >> 2;
    int bbase = (blockIdx.x & 3) << 8;
    int b = bbase + threadIdx.x;

    // load x[b, k*12 .. +12] as 3 float4 (aligned: 48B and 7680B strides)
    const float4* xr4 = (const float4*)(x + (size_t)b * 1920 + k * WS);
    float4 x0 = xr4[0], x1 = xr4[1], x2 = xr4[2];
    float xv[WS] = {x0.x, x0.y, x0.z, x0.w, x1.x, x1.y, x1.z, x1.w,
                    x2.x, x2.y, x2.z, x2.w};

    const float* ew = enc_W + k * (WS * WS);
    float xs[WS];
#pragma unroll
    for (int o = 0; o < WS; ++o) {
        float a = enc_b[k * WS + o];
#pragma unroll
        for (int i = 0; i < WS; ++i) a = fmaf(xv[i], ew[i * WS + o], a);
        xs[o] = fmaxf(a, 0.0f);
    }

    float* sgr = sg + threadIdx.x * 37;
#pragma unroll
    for (int g = 0; g < G; ++g) {
        float a = bih[g];
#pragma unroll
        for (int o = 0; o < WS; ++o) a = fmaf(xs[o], Wih[g * WS + o], a);
        sgr[g] = a;
    }
    __syncthreads();

    // coalesced copy out: 256*36 floats contiguous in g_gi1
    float* dst = g_gi1 + ((size_t)k * Bn + bbase) * G;
    for (int i = threadIdx.x; i < 256 * G; i += 256) {
        int bl = i / G;
        int g = i - bl * G;
        dst[i] = sg[bl * 37 + g];
    }
}

// ---------------------------------------------------------------------------
// Kernel 2: pe gate table: pe_gi[k][g] = (pe[k]+sin(k)) @ Wih[g]
// ---------------------------------------------------------------------------
__global__ void pegi_kernel(const float* __restrict__ Wih) {
    int k = threadIdx.x;
    if (k >= Kseg) return;
    float pe[WS];
    const float c = -9.210340371976184f / 12.0f;   // -ln(10000)/d
#pragma unroll
    for (int j = 0; j < 6; ++j) {
        float div = expf(c * (float)(2 * j));
        float ang = (float)k * div;
        pe[2 * j]     = sinf(ang);
        pe[2 * j + 1] = cosf(ang);
    }
    float ch = sinf((float)k);
#pragma unroll
    for (int o = 0; o < WS; ++o) pe[o] += ch;
#pragma unroll
    for (int g = 0; g < G; ++g) {
        float a = 0.0f;
#pragma unroll
        for (int o = 0; o < WS; ++o) a = fmaf(pe[o], Wih[g * WS + o], a);
        g_pegi[k * G + g] = a;
    }
}

// ---------------------------------------------------------------------------
// Kernel 3: decoder fold. Weff[k] = W1[k]@W2[k], beff[k] = b1[k]@W2[k]+b2[k].
// 8 accumulators + float4 global loads to break the serial FMA chain.
// ---------------------------------------------------------------------------
__global__ void __launch_bounds__(256) weff_kernel(
        const float* __restrict__ dec_W1,
        const float* __restrict__ dec_b1,
        const float* __restrict__ dec_W2,
        const float* __restrict__ dec_b2) {
    __shared__ float w2s[DH * WS];   // 48 KB
    int k = blockIdx.x;
    const float4* W24 = (const float4*)(dec_W2 + (size_t)k * DH * WS);
    float4* w2s4 = (float4*)w2s;
    for (int i = threadIdx.x; i < DH * WS / 4; i += 256) w2s4[i] = W24[i];
    __syncthreads();

    int t = threadIdx.x;
    if (t < 144) {
        int d = t / WS, o = t - (t / WS) * WS;
        const float4* w14 = (const float4*)(dec_W1 + ((size_t)k * WS + d) * DH);
        float a0 = 0.f, a1 = 0.f, a2 = 0.f, a3 = 0.f;
        float a4 = 0.f, a5 = 0.f, a6 = 0.f, a7 = 0.f;
        for (int q = 0; q < DH / 4; q += 2) {
            float4 u = w14[q], v = w14[q + 1];
            int h = q * 4;
            a0 = fmaf(u.x, w2s[(h + 0) * WS + o], a0);
            a1 = fmaf(u.y, w2s[(h + 1) * WS + o], a1);
            a2 = fmaf(u.z, w2s[(h + 2) * WS + o], a2);
            a3 = fmaf(u.w, w2s[(h + 3) * WS + o], a3);
            a4 = fmaf(v.x, w2s[(h + 4) * WS + o], a4);
            a5 = fmaf(v.y, w2s[(h + 5) * WS + o], a5);
            a6 = fmaf(v.z, w2s[(h + 6) * WS + o], a6);
            a7 = fmaf(v.w, w2s[(h + 7) * WS + o], a7);
        }
        g_weff[k * 144 + d * WS + o] =
            ((a0 + a1) + (a2 + a3)) + ((a4 + a5) + (a6 + a7));
    } else if (t < 156) {
        int o = t - 144;
        const float4* b14 = (const float4*)(dec_b1 + (size_t)k * DH);
        float a0 = dec_b2[k * WS + o], a1 = 0.f, a2 = 0.f, a3 = 0.f;
        for (int q = 0; q < DH / 4; ++q) {
            float4 u = b14[q];
            int h = q * 4;
            a0 = fmaf(u.x, w2s[(h + 0) * WS + o], a0);
            a1 = fmaf(u.y, w2s[(h + 1) * WS + o], a1);
            a2 = fmaf(u.z, w2s[(h + 2) * WS + o], a2);
            a3 = fmaf(u.w, w2s[(h + 3) * WS + o], a3);
        }
        g_beff[k * WS + o] = (a0 + a1) + (a2 + a3);
    }
}

// ---------------------------------------------------------------------------
// Kernel 4: recurrence. 16-lane group handles TWO batch rows (R=2): two
// independent dependency chains per thread overlap the latency. gi loads
// software-pipelined 3 steps ahead (>= L2 latency).
// ---------------------------------------------------------------------------
__device__ __forceinline__ float fast_sigmoid(float v) {
    return __fdividef(1.0f, 1.0f + __expf(-v));
}
__device__ __forceinline__ float fast_tanh(float v) {
    float e = __expf(-2.0f * v);
    return __fdividef(1.0f - e, 1.0f + e);
}

__device__ __forceinline__ float gru_step(float h, float gr, float gz, float gn,
                                          const float wr[12], const float wz[12],
                                          const float wn[12],
                                          float br, float bz, float bn) {
    float a0 = br, a1 = 0.f, b0 = bz, b1 = 0.f, c0 = bn, c1 = 0.f;
#pragma unroll
    for (int i = 0; i < 12; i += 2) {
        float h0 = __shfl_sync(0xffffffffu, h, i, 16);
        float h1 = __shfl_sync(0xffffffffu, h, i + 1, 16);
        a0 = fmaf(wr[i], h0, a0); a1 = fmaf(wr[i + 1], h1, a1);
        b0 = fmaf(wz[i], h0, b0); b1 = fmaf(wz[i + 1], h1, b1);
        c0 = fmaf(wn[i], h0, c0); c1 = fmaf(wn[i + 1], h1, c1);
    }
    float r = fast_sigmoid(gr + (a0 + a1));
    float z = fast_sigmoid(gz + (b0 + b1));
    float n = fast_tanh(fmaf(r, c0 + c1, gn));
    return fmaf(z, h - n, n);
}

#define STRIDE_T (Bn * G)

__global__ void __launch_bounds__(128) rnn_kernel(const float* __restrict__ Whh,
                                                  const float* __restrict__ bhh) {
    __shared__ float pegis[Kseg * G];   // 23 KB
    int lane16 = threadIdx.x & 15;
    int grp = blockIdx.x * 8 + (threadIdx.x >> 4);   // 0..511
    int rowA = grp * 2, rowB = rowA + 1;
    bool act = (lane16 < WS);
    int j = act ? lane16 : 0;

    float wr[12], wz[12], wn[12];
#pragma unroll
    for (int i = 0; i < 12; ++i) {
        wr[i] = Whh[j * 12 + i];
        wz[i] = Whh[(12 + j) * 12 + i];
        wn[i] = Whh[(24 + j) * 12 + i];
    }
    float br = bhh[j], bz = bhh[12 + j], bn = bhh[24 + j];

    for (int i = threadIdx.x; i < Kseg * G; i += 128) pegis[i] = g_pegi[i];
    __syncthreads();

    const float* gA = g_gi1 + rowA * G;
    const float* gB = g_gi1 + rowB * G;
    float hA = 0.0f, hB = 0.0f;

    // 3-deep prefetch ring (explicit registers)
    float rA0, zA0, nA0, rA1, zA1, nA1, rA2, zA2, nA2;
    float rB0, zB0, nB0, rB1, zB1, nB1, rB2, zB2, nB2;

#define LOADG(dst_r, dst_z, dst_n, base, tt)                 \
    { const float* _p = (base) + (size_t)(tt) * STRIDE_T;    \
      dst_r = _p[j]; dst_z = _p[12 + j]; dst_n = _p[24 + j]; }

    // ---------------- phase 1: first GRU (keep only final h) ---------------
    LOADG(rA0, zA0, nA0, gA, 0); LOADG(rB0, zB0, nB0, gB, 0);
    LOADG(rA1, zA1, nA1, gA, 1); LOADG(rB1, zB1, nB1, gB, 1);
    LOADG(rA2, zA2, nA2, gA, 2); LOADG(rB2, zB2, nB2, gB, 2);
    for (int t = 0; t < Kseg; ++t) {
        float crA = rA0, czA = zA0, cnA = nA0;
        float crB = rB0, czB = zB0, cnB = nB0;
        rA0 = rA1; zA0 = zA1; nA0 = nA1;  rA1 = rA2; zA1 = zA2; nA1 = nA2;
        rB0 = rB1; zB0 = zB1; nB0 = nB1;  rB1 = rB2; zB1 = zB2; nB1 = nB2;
        int tp = (t + 3 < Kseg) ? t + 3 : Kseg - 1;
        LOADG(rA2, zA2, nA2, gA, tp); LOADG(rB2, zB2, nB2, gB, tp);

        hA = gru_step(hA, crA, czA, cnA, wr, wz, wn, br, bz, bn);
        hB = gru_step(hB, crB, czB, cnB, wr, wz, wn, br, bz, bn);
    }

    // ---------------- phase 2: second GRU (emit all outputs) ---------------
    float* yoA = g_ys + (size_t)rowA * (Kseg * WS);
    float* yoB = g_ys + (size_t)rowB * (Kseg * WS);
    LOADG(rA0, zA0, nA0, gA, 0); LOADG(rB0, zB0, nB0, gB, 0);
    LOADG(rA1, zA1, nA1, gA, 1); LOADG(rB1, zB1, nB1, gB, 1);
    LOADG(rA2, zA2, nA2, gA, 2); LOADG(rB2, zB2, nB2, gB, 2);
    for (int t = 0; t < Kseg; ++t) {
        const float* p = pegis + t * G;
        float pr = p[j], pz = p[12 + j], pn = p[24 + j];
        float crA = rA0 + pr, czA = zA0 + pz, cnA = nA0 + pn;
        float crB = rB0 + pr, czB = zB0 + pz, cnB = nB0 + pn;
        rA0 = rA1; zA0 = zA1; nA0 = nA1;  rA1 = rA2; zA1 = zA2; nA1 = nA2;
        rB0 = rB1; zB0 = zB1; nB0 = nB1;  rB1 = rB2; zB1 = zB2; nB1 = nB2;
        int tp = (t + 3 < Kseg) ? t + 3 : Kseg - 1;
        LOADG(rA2, zA2, nA2, gA, tp); LOADG(rB2, zB2, nB2, gB, tp);

        hA = gru_step(hA, crA, czA, cnA, wr, wz, wn, br, bz, bn);
        hB = gru_step(hB, crB, czB, cnB, wr, wz, wn, br, bz, bn);
        if (act) {
            yoA[t * WS + j] = hA;
            yoB[t * WS + j] = hB;
        }
    }
#undef LOADG
}

// ---------------------------------------------------------------------------
// Kernel 5: folded decoder: out[b,k,:] = ys[b,k,:] @ Weff[k] + beff[k]
// float4 loads/stores; 12 register accumulators, d-outer with vector w loads.
// ---------------------------------------------------------------------------
__global__ void __launch_bounds__(256) dec_kernel(float* __restrict__ out) {
    int tid = blockIdx.x * blockDim.x + threadIdx.x;
    int b = tid / Kseg;
    int k = tid - b * Kseg;
    if (b >= Bn) return;

    const float4* hp4 = (const float4*)(g_ys + ((size_t)b * Kseg + k) * WS);
    float4 h0 = hp4[0], h1 = hp4[1], h2 = hp4[2];
    float hv[WS] = {h0.x, h0.y, h0.z, h0.w, h1.x, h1.y, h1.z, h1.w,
                    h2.x, h2.y, h2.z, h2.w};

    const float4* be4 = (const float4*)(g_beff + k * WS);
    float4 b0 = be4[0], b1 = be4[1], b2 = be4[2];
    float acc[WS] = {b0.x, b0.y, b0.z, b0.w, b1.x, b1.y, b1.z, b1.w,
                     b2.x, b2.y, b2.z, b2.w};

    const float4* w4 = (const float4*)(g_weff + k * 144);
#pragma unroll
    for (int d = 0; d < WS; ++d) {
        float4 wa = w4[d * 3 + 0], wb = w4[d * 3 + 1], wc = w4[d * 3 + 2];
        float hd = hv[d];
        acc[0] = fmaf(hd, wa.x, acc[0]); acc[1] = fmaf(hd, wa.y, acc[1]);
        acc[2] = fmaf(hd, wa.z, acc[2]); acc[3] = fmaf(hd, wa.w, acc[3]);
        acc[4] = fmaf(hd, wb.x, acc[4]); acc[5] = fmaf(hd, wb.y, acc[5]);
        acc[6] = fmaf(hd, wb.z, acc[6]); acc[7] = fmaf(hd, wb.w, acc[7]);
        acc[8] = fmaf(hd, wc.x, acc[8]); acc[9] = fmaf(hd, wc.y, acc[9]);
        acc[10] = fmaf(hd, wc.z, acc[10]); acc[11] = fmaf(hd, wc.w, acc[11]);
    }

    float4* op4 = (float4*)(out + (size_t)b * 1920 + k * WS);
    op4[0] = make_float4(acc[0], acc[1], acc[2], acc[3]);
    op4[1] = make_float4(acc[4], acc[5], acc[6], acc[7]);
    op4[2] = make_float4(acc[8], acc[9], acc[10], acc[11]);
}

// ---------------------------------------------------------------------------
extern "C" void kernel_launch(void* const* d_in, const int* in_sizes, int n_in,
                              void* d_out, int out_size) {
    const float* x     = (const float*)d_in[0];
    const float* enc_W = (const float*)d_in[1];
    const float* enc_b = (const float*)d_in[2];
    const float* Wih   = (const float*)d_in[3];
    const float* Whh   = (const float*)d_in[4];
    const float* bih   = (const float*)d_in[5];
    const float* bhh   = (const float*)d_in[6];
    const float* dW1   = (const float*)d_in[7];
    const float* db1   = (const float*)d_in[8];
    const float* dW2   = (const float*)d_in[9];
    const float* db2   = (const float*)d_in[10];
    float* out = (float*)d_out;

    enc_gi_kernel<<<640, 256>>>(x, enc_W, enc_b, Wih, bih);
    pegi_kernel<<<1, 192>>>(Wih);
    weff_kernel<<<Kseg, 256>>>(dW1, db1, dW2, db2);
    rnn_kernel<<<64, 128>>>(Whh, bhh);      // 512 groups x 2 rows
    dec_kernel<<<640, 256>>>(out);
}

// round 4
// speedup vs baseline: 1.5528x; 1.4221x over previous
#include <cuda_runtime.h>

#define Bn   1024
#define Kseg 160
#define WS   12
#define G    36
#define DH   1024
#define TPAD 164            // Kseg + 4 prefetch pad
#define STR4 (Bn * WS)      // float4 stride between t slots

// Scratch (static device globals — no allocation)
__device__ float4 g_gi[TPAD * Bn * WS];    // [t][b][j] = {r,z,n,0} gates (bih+bhh_rz folded)
__device__ float4 g_pegi4[Kseg * WS];      // [t][j] = {pr,pz,pn,0}
__device__ float  g_weff[Kseg * WS * WS];  // folded decoder W1@W2 per segment
__device__ float  g_beff[Kseg * WS];       // folded decoder bias
__device__ float  g_ysT[Bn * WS * Kseg];   // [b][j][t]  GRU2 outputs (transposed)

// ---------------------------------------------------------------------------
// Kernel 1: encoder relu(xb@enc_W+enc_b) and gi = xs@Wih^T + bih (+bhh for r,z)
// ---------------------------------------------------------------------------
__global__ void __launch_bounds__(256) enc_gi_kernel(
        const float* __restrict__ x,
        const float* __restrict__ enc_W,
        const float* __restrict__ enc_b,
        const float* __restrict__ Wih,
        const float* __restrict__ bih,
        const float* __restrict__ bhh) {
    __shared__ float sg[256 * 37];          // pad 36->37: conflict-free STS
    int k = blockIdx.x >> 2;
    int bbase = (blockIdx.x & 3) << 8;
    int b = bbase + threadIdx.x;

    const float4* xr4 = (const float4*)(x + (size_t)b * 1920 + k * WS);
    float4 x0 = xr4[0], x1 = xr4[1], x2 = xr4[2];
    float xv[WS] = {x0.x, x0.y, x0.z, x0.w, x1.x, x1.y, x1.z, x1.w,
                    x2.x, x2.y, x2.z, x2.w};

    const float* ew = enc_W + k * (WS * WS);
    float xs[WS];
#pragma unroll
    for (int o = 0; o < WS; ++o) {
        float a = enc_b[k * WS + o];
#pragma unroll
        for (int i = 0; i < WS; ++i) a = fmaf(xv[i], ew[i * WS + o], a);
        xs[o] = fmaxf(a, 0.0f);
    }

    float* sgr = sg + threadIdx.x * 37;
#pragma unroll
    for (int g = 0; g < G; ++g) {
        float a = bih[g] + ((g < 24) ? bhh[g] : 0.0f);   // fold bhh_r, bhh_z
#pragma unroll
        for (int o = 0; o < WS; ++o) a = fmaf(xs[o], Wih[g * WS + o], a);
        sgr[g] = a;
    }
    __syncthreads();

    // write out as float4 {r,z,n,0}
    float4* dst = g_gi + ((size_t)k * Bn + bbase) * WS;
    for (int i = threadIdx.x; i < 256 * WS; i += 256) {
        int bl = i / WS;
        int j = i - bl * WS;
        const float* s = sg + bl * 37 + j;
        dst[i] = make_float4(s[0], s[12], s[24], 0.0f);
    }
}

// ---------------------------------------------------------------------------
// Kernel 2: pe gate table as float4 [k][j] = {pr,pz,pn,0}
// ---------------------------------------------------------------------------
__global__ void pegi_kernel(const float* __restrict__ Wih) {
    int k = threadIdx.x;
    if (k >= Kseg) return;
    float pe[WS];
    const float c = -9.210340371976184f / 12.0f;   // -ln(10000)/d
#pragma unroll
    for (int j = 0; j < 6; ++j) {
        float div = expf(c * (float)(2 * j));
        float ang = (float)k * div;
        pe[2 * j]     = sinf(ang);
        pe[2 * j + 1] = cosf(ang);
    }
    float ch = sinf((float)k);
#pragma unroll
    for (int o = 0; o < WS; ++o) pe[o] += ch;
    float pg[G];
#pragma unroll
    for (int g = 0; g < G; ++g) {
        float a = 0.0f;
#pragma unroll
        for (int o = 0; o < WS; ++o) a = fmaf(pe[o], Wih[g * WS + o], a);
        pg[g] = a;
    }
#pragma unroll
    for (int j = 0; j < WS; ++j)
        g_pegi4[k * WS + j] = make_float4(pg[j], pg[12 + j], pg[24 + j], 0.0f);
}

// ---------------------------------------------------------------------------
// Kernel 3: decoder fold. Weff[k] = W1[k]@W2[k], beff[k] = b1[k]@W2[k]+b2[k].
// ---------------------------------------------------------------------------
__global__ void __launch_bounds__(256) weff_kernel(
        const float* __restrict__ dec_W1,
        const float* __restrict__ dec_b1,
        const float* __restrict__ dec_W2,
        const float* __restrict__ dec_b2) {
    __shared__ float w2s[DH * WS];   // 48 KB
    int k = blockIdx.x;
    const float4* W24 = (const float4*)(dec_W2 + (size_t)k * DH * WS);
    float4* w2s4 = (float4*)w2s;
    for (int i = threadIdx.x; i < DH * WS / 4; i += 256) w2s4[i] = W24[i];
    __syncthreads();

    int t = threadIdx.x;
    if (t < 144) {
        int d = t / WS, o = t - (t / WS) * WS;
        const float4* w14 = (const float4*)(dec_W1 + ((size_t)k * WS + d) * DH);
        float a0 = 0.f, a1 = 0.f, a2 = 0.f, a3 = 0.f;
        float a4 = 0.f, a5 = 0.f, a6 = 0.f, a7 = 0.f;
        for (int q = 0; q < DH / 4; q += 2) {
            float4 u = w14[q], v = w14[q + 1];
            int h = q * 4;
            a0 = fmaf(u.x, w2s[(h + 0) * WS + o], a0);
            a1 = fmaf(u.y, w2s[(h + 1) * WS + o], a1);
            a2 = fmaf(u.z, w2s[(h + 2) * WS + o], a2);
            a3 = fmaf(u.w, w2s[(h + 3) * WS + o], a3);
            a4 = fmaf(v.x, w2s[(h + 4) * WS + o], a4);
            a5 = fmaf(v.y, w2s[(h + 5) * WS + o], a5);
            a6 = fmaf(v.z, w2s[(h + 6) * WS + o], a6);
            a7 = fmaf(v.w, w2s[(h + 7) * WS + o], a7);
        }
        g_weff[k * 144 + d * WS + o] =
            ((a0 + a1) + (a2 + a3)) + ((a4 + a5) + (a6 + a7));
    } else if (t < 156) {
        int o = t - 144;
        const float4* b14 = (const float4*)(dec_b1 + (size_t)k * DH);
        float a0 = dec_b2[k * WS + o], a1 = 0.f, a2 = 0.f, a3 = 0.f;
        for (int q = 0; q < DH / 4; ++q) {
            float4 u = b14[q];
            int h = q * 4;
            a0 = fmaf(u.x, w2s[(h + 0) * WS + o], a0);
            a1 = fmaf(u.y, w2s[(h + 1) * WS + o], a1);
            a2 = fmaf(u.z, w2s[(h + 2) * WS + o], a2);
            a3 = fmaf(u.w, w2s[(h + 3) * WS + o], a3);
        }
        g_beff[k * WS + o] = (a0 + a1) + (a2 + a3);
    }
}

// ---------------------------------------------------------------------------
// Kernel 4: recurrence. ONE row per 16-lane group (two rows per warp run
// SIMD across the warp halves). float4 gi loads, 4-deep rotating prefetch,
// float4 pegi from smem, 4-step buffered float4 stores.
// ---------------------------------------------------------------------------
__device__ __forceinline__ float fast_sigmoid(float v) {
    return __fdividef(1.0f, 1.0f + __expf(-v));
}
__device__ __forceinline__ float fast_tanh(float v) {
    float e = __expf(-2.0f * v);
    return __fdividef(1.0f - e, 1.0f + e);
}

// gr,gz have all biases folded; bn stays with the r-scaled recurrent term
__device__ __forceinline__ float gstep(float h, float gr, float gz, float gn,
                                       float bn,
                                       const float wr[12], const float wz[12],
                                       const float wn[12]) {
    float a0 = gr, a1 = 0.f, b0 = gz, b1 = 0.f, c0 = bn, c1 = 0.f;
#pragma unroll
    for (int i = 0; i < 12; i += 2) {
        float h0 = __shfl_sync(0xffffffffu, h, i, 16);
        float h1 = __shfl_sync(0xffffffffu, h, i + 1, 16);
        a0 = fmaf(wr[i], h0, a0); a1 = fmaf(wr[i + 1], h1, a1);
        b0 = fmaf(wz[i], h0, b0); b1 = fmaf(wz[i + 1], h1, b1);
        c0 = fmaf(wn[i], h0, c0); c1 = fmaf(wn[i + 1], h1, c1);
    }
    float r = fast_sigmoid(a0 + a1);
    float z = fast_sigmoid(b0 + b1);
    float n = fast_tanh(fmaf(r, c0 + c1, gn));
    return fmaf(z, h - n, n);
}

__global__ void __launch_bounds__(128) rnn_kernel(const float* __restrict__ Whh,
                                                  const float* __restrict__ bhh) {
    __shared__ float4 pegis[Kseg * WS];   // 30 KB
    int lane16 = threadIdx.x & 15;
    int row = blockIdx.x * 8 + (threadIdx.x >> 4);   // 0..1023
    bool act = (lane16 < WS);
    int j = act ? lane16 : 0;

    float wr[12], wz[12], wn[12];
#pragma unroll
    for (int i = 0; i < 12; ++i) {
        wr[i] = Whh[j * 12 + i];
        wz[i] = Whh[(12 + j) * 12 + i];
        wn[i] = Whh[(24 + j) * 12 + i];
    }
    float bn = bhh[24 + j];

    for (int i = threadIdx.x; i < Kseg * WS; i += 128) pegis[i] = g_pegi4[i];
    __syncthreads();

    const float4* pA = g_gi + (size_t)row * WS + j;
    float h = 0.0f;

    float4 a0, a1, a2, a3;
    const float4* q;

    // ---------------- phase 1: first GRU (keep only final h) ---------------
    a0 = pA[0];
    a1 = pA[STR4];
    a2 = pA[2 * STR4];
    a3 = pA[3 * STR4];
    q = pA + 4 * STR4;
    for (int t = 0; t < Kseg; t += 4) {
        h = gstep(h, a0.x, a0.y, a0.z, bn, wr, wz, wn);
        a0 = q[0];
        h = gstep(h, a1.x, a1.y, a1.z, bn, wr, wz, wn);
        a1 = q[STR4];
        h = gstep(h, a2.x, a2.y, a2.z, bn, wr, wz, wn);
        a2 = q[2 * STR4];
        h = gstep(h, a3.x, a3.y, a3.z, bn, wr, wz, wn);
        a3 = q[3 * STR4];
        q += 4 * STR4;
    }

    // ---------------- phase 2: second GRU (emit all outputs) ---------------
    float* yA = g_ysT + ((size_t)row * WS + j) * Kseg;
    a0 = pA[0];
    a1 = pA[STR4];
    a2 = pA[2 * STR4];
    a3 = pA[3 * STR4];
    q = pA + 4 * STR4;
    const float4* pg = pegis + j;
    for (int t = 0; t < Kseg; t += 4) {
        float4 p0 = pg[0], p1 = pg[WS], p2 = pg[2 * WS], p3 = pg[3 * WS];
        pg += 4 * WS;
        float4 ya;
        h = gstep(h, a0.x + p0.x, a0.y + p0.y, a0.z + p0.z, bn, wr, wz, wn);
        ya.x = h;
        a0 = q[0];
        h = gstep(h, a1.x + p1.x, a1.y + p1.y, a1.z + p1.z, bn, wr, wz, wn);
        ya.y = h;
        a1 = q[STR4];
        h = gstep(h, a2.x + p2.x, a2.y + p2.y, a2.z + p2.z, bn, wr, wz, wn);
        ya.z = h;
        a2 = q[2 * STR4];
        h = gstep(h, a3.x + p3.x, a3.y + p3.y, a3.z + p3.z, bn, wr, wz, wn);
        ya.w = h;
        a3 = q[3 * STR4];
        q += 4 * STR4;
        if (act) *(float4*)(yA + t) = ya;
    }
}

// ---------------------------------------------------------------------------
// Kernel 5: folded decoder: out[b,k,:] = ysT[b,:,k] @ Weff[k] + beff[k]
// ---------------------------------------------------------------------------
__global__ void __launch_bounds__(256) dec_kernel(float* __restrict__ out) {
    int tid = blockIdx.x * blockDim.x + threadIdx.x;
    int b = tid / Kseg;
    int k = tid - b * Kseg;
    if (b >= Bn) return;

    const float* yb = g_ysT + (size_t)b * WS * Kseg + k;
    float hv[WS];
#pragma unroll
    for (int d = 0; d < WS; ++d) hv[d] = yb[d * Kseg];

    const float4* be4 = (const float4*)(g_beff + k * WS);
    float4 b0 = be4[0], b1 = be4[1], b2 = be4[2];
    float acc[WS] = {b0.x, b0.y, b0.z, b0.w, b1.x, b1.y, b1.z, b1.w,
                     b2.x, b2.y, b2.z, b2.w};

    const float4* w4 = (const float4*)(g_weff + k * 144);
#pragma unroll
    for (int d = 0; d < WS; ++d) {
        float4 wa = w4[d * 3 + 0], wb = w4[d * 3 + 1], wc = w4[d * 3 + 2];
        float hd = hv[d];
        acc[0] = fmaf(hd, wa.x, acc[0]); acc[1] = fmaf(hd, wa.y, acc[1]);
        acc[2] = fmaf(hd, wa.z, acc[2]); acc[3] = fmaf(hd, wa.w, acc[3]);
        acc[4] = fmaf(hd, wb.x, acc[4]); acc[5] = fmaf(hd, wb.y, acc[5]);
        acc[6] = fmaf(hd, wb.z, acc[6]); acc[7] = fmaf(hd, wb.w, acc[7]);
        acc[8] = fmaf(hd, wc.x, acc[8]); acc[9] = fmaf(hd, wc.y, acc[9]);
        acc[10] = fmaf(hd, wc.z, acc[10]); acc[11] = fmaf(hd, wc.w, acc[11]);
    }

    float4* op4 = (float4*)(out + (size_t)b * 1920 + k * WS);
    op4[0] = make_float4(acc[0], acc[1], acc[2], acc[3]);
    op4[1] = make_float4(acc[4], acc[5], acc[6], acc[7]);
    op4[2] = make_float4(acc[8], acc[9], acc[10], acc[11]);
}

// ---------------------------------------------------------------------------
extern "C" void kernel_launch(void* const* d_in, const int* in_sizes, int n_in,
                              void* d_out, int out_size) {
    const float* x     = (const float*)d_in[0];
    const float* enc_W = (const float*)d_in[1];
    const float* enc_b = (const float*)d_in[2];
    const float* Wih   = (const float*)d_in[3];
    const float* Whh   = (const float*)d_in[4];
    const float* bih   = (const float*)d_in[5];
    const float* bhh   = (const float*)d_in[6];
    const float* dW1   = (const float*)d_in[7];
    const float* db1   = (const float*)d_in[8];
    const float* dW2   = (const float*)d_in[9];
    const float* db2   = (const float*)d_in[10];
    float* out = (float*)d_out;

    enc_gi_kernel<<<640, 256>>>(x, enc_W, enc_b, Wih, bih, bhh);
    pegi_kernel<<<1, 192>>>(Wih);
    weff_kernel<<<Kseg, 256>>>(dW1, db1, dW2, db2);
    rnn_kernel<<<128, 128>>>(Whh, bhh);      // 1024 rows, one row per 16-lane group
    dec_kernel<<<640, 256>>>(out);
}